// round 15
// baseline (speedup 1.0000x reference)
#include <cuda_runtime.h>
#include <cuda_fp16.h>
#include <math.h>
#include <stdint.h>

#define N_NODES 50000
#define N_EDGES 800000
#define IN_CH   128
#define HID     256
#define MPAD    50048   // 391 * 128
#define CSTRIDE 128     // padded-CSR slots per node (P(deg>=128) ~ 0)

// ---------------- scratch (device globals; zero-initialized bss) ----------------
__device__ int   g_cnt[N_NODES];     // invariant: all-zero at kernel_launch entry
__device__ int   g_deg[N_NODES];
__device__ int   g_col[(size_t)N_NODES * CSTRIDE];
__device__ float g_dinv[N_NODES];

__device__ __half g_x16[(size_t)N_NODES * IN_CH];   // x rounded to fp16
__device__ __half g_a1[(size_t)MPAD * IN_CH];       // agg1 out (pad rows stay 0)
__device__ __half g_h[(size_t)MPAD * HID];          // relu(a1@W1+b1), fp16
__device__ __half g_a2[(size_t)MPAD * HID];         // agg2 out (pad rows stay 0)
__device__ __half g_w1t[HID * IN_CH];               // W1^T fp16 [256][128]
__device__ __half g_w2t[HID * HID];                 // W2^T fp16 [256][256]

// ---------------- helpers ----------------
__device__ __forceinline__ uint32_t smem_to_u32(const void* p) {
    uint32_t a;
    asm("{ .reg .u64 t; cvta.to.shared.u64 t, %1; cvt.u32.u64 %0, t; }" : "=r"(a) : "l"(p));
    return a;
}
#define CP_ASYNC16(dst, src) \
    asm volatile("cp.async.cg.shared.global [%0], [%1], 16;" :: "r"(dst), "l"(src))
#define CP_COMMIT() asm volatile("cp.async.commit_group;" ::: "memory")
#define CP_WAIT1()  asm volatile("cp.async.wait_group 1;" ::: "memory")

#define MMA_F16(acc, a, b) \
    asm volatile("mma.sync.aligned.m16n8k16.row.col.f32.f16.f16.f32 " \
                 "{%0,%1,%2,%3},{%4,%5,%6,%7},{%8,%9},{%0,%1,%2,%3};" \
                 : "+f"(acc[0]), "+f"(acc[1]), "+f"(acc[2]), "+f"(acc[3]) \
                 : "r"(a[0]), "r"(a[1]), "r"(a[2]), "r"(a[3]), "r"(b[0]), "r"(b[1]))

// ---------------- graph build: edge-parallel, ILP=4, dtype probe inlined ------------
// int64 little-endian with values < 50000 => first 128 odd int32 words all zero.
#define EILP 4
__global__ void __launch_bounds__(256)
histfill_kernel(const int* __restrict__ ei_raw) {
    __shared__ int s_bad;
    if (threadIdx.x == 0) s_bad = 0;
    __syncthreads();
    if (threadIdx.x < 128 && ei_raw[2 * threadIdx.x + 1] != 0) s_bad = 1;
    __syncthreads();
    bool is64 = (s_bad == 0);

    int base = blockIdx.x * (256 * EILP) + threadIdx.x;
    int s[EILP], d[EILP];
    bool ok[EILP];
#pragma unroll
    for (int t = 0; t < EILP; t++) {
        int e = base + t * 256;
        ok[t] = (e < N_EDGES);
        if (ok[t]) {
            if (is64) {
                s[t] = (int)((const long long*)ei_raw)[e];
                d[t] = (int)((const long long*)ei_raw)[(long long)N_EDGES + e];
            } else {
                s[t] = ei_raw[e];
                d[t] = ei_raw[N_EDGES + e];
            }
        }
    }
    int pos[EILP];
#pragma unroll
    for (int t = 0; t < EILP; t++)
        if (ok[t]) pos[t] = atomicAdd(&g_cnt[d[t]], 1);
#pragma unroll
    for (int t = 0; t < EILP; t++)
        if (ok[t] && pos[t] < CSTRIDE) g_col[(size_t)d[t] * CSTRIDE + pos[t]] = s[t];
}
// deg/dinv + reset cnt for next graph replay
__global__ void dinv_kernel() {
    cudaGridDependencySynchronize();
    int i = blockIdx.x * blockDim.x + threadIdx.x;
    if (i < N_NODES) {
        int c = g_cnt[i];
        g_deg[i]  = (c < CSTRIDE) ? c : CSTRIDE;
        g_dinv[i] = rsqrtf((float)(c + 1));
        g_cnt[i]  = 0;
    }
}

// ---------------- x -> fp16 ----------------
__global__ void x2h_kernel(const float* __restrict__ x, __half* __restrict__ xh) {
    int i = blockIdx.x * blockDim.x + threadIdx.x;   // one float4 per thread
    if (i < N_NODES * IN_CH / 4) {
        float4 v = ((const float4*)x)[i];
        ((__half2*)xh)[2 * i]     = __floats2half2_rn(v.x, v.y);
        ((__half2*)xh)[2 * i + 1] = __floats2half2_rn(v.z, v.w);
    }
}

// ---------------- W round+transpose: W [K][256] fp32 -> WT [256][K] fp16 ----------------
__global__ void roundW_kernel(const float* __restrict__ W, int K, __half* __restrict__ WT) {
    int idx = blockIdx.x * 256 + threadIdx.x;
    if (idx < K * 256) {
        int k = idx >> 8, n = idx & 255;
        WT[(size_t)n * K + k] = __float2half_rn(W[idx]);
    }
}

// ---------------- warp-per-node aggregation (padded CSR) ----------------
// out[v] = dinv[v]*sum dinv[s]*feat[s] + dinv[v]^2*feat[v]; 8 nodes per 256-thr block.

// layer 1: F=128 -> each lane owns 8B (uint2 = 2 half2)
__global__ void __launch_bounds__(256)
agg1_kernel(const __half* __restrict__ feat, __half* __restrict__ A) {
    cudaGridDependencySynchronize();
    int node = blockIdx.x * 8 + (threadIdx.x >> 5);
    if (node >= N_NODES) return;
    int lane = threadIdx.x & 31;
    int deg = g_deg[node];
    const int* cbase = g_col + (size_t)node * CSTRIDE;

    const uint2* fb = (const uint2*)feat;   // 32 uint2 per row
    float a0 = 0.f, a1 = 0.f, a2 = 0.f, a3 = 0.f;

    for (int cs = 0; cs < deg; cs += 32) {
        int nn = deg - cs; if (nn > 32) nn = 32;
        int idx = 0; float w = 0.f;
        if (lane < nn) { idx = cbase[cs + lane]; w = g_dinv[idx]; }
        int j = 0;
        for (; j + 4 <= nn; j += 4) {
            int   s0 = __shfl_sync(0xffffffffu, idx, j);
            int   s1 = __shfl_sync(0xffffffffu, idx, j + 1);
            int   s2 = __shfl_sync(0xffffffffu, idx, j + 2);
            int   s3 = __shfl_sync(0xffffffffu, idx, j + 3);
            float w0 = __shfl_sync(0xffffffffu, w, j);
            float w1 = __shfl_sync(0xffffffffu, w, j + 1);
            float w2 = __shfl_sync(0xffffffffu, w, j + 2);
            float w3 = __shfl_sync(0xffffffffu, w, j + 3);
            uint2 v0 = fb[(size_t)s0 * 32 + lane];
            uint2 v1 = fb[(size_t)s1 * 32 + lane];
            uint2 v2 = fb[(size_t)s2 * 32 + lane];
            uint2 v3 = fb[(size_t)s3 * 32 + lane];
            float2 l0 = __half22float2(*(__half2*)&v0.x), h0 = __half22float2(*(__half2*)&v0.y);
            float2 l1 = __half22float2(*(__half2*)&v1.x), h1 = __half22float2(*(__half2*)&v1.y);
            float2 l2 = __half22float2(*(__half2*)&v2.x), h2 = __half22float2(*(__half2*)&v2.y);
            float2 l3 = __half22float2(*(__half2*)&v3.x), h3 = __half22float2(*(__half2*)&v3.y);
            a0 += w0 * l0.x + w1 * l1.x + w2 * l2.x + w3 * l3.x;
            a1 += w0 * l0.y + w1 * l1.y + w2 * l2.y + w3 * l3.y;
            a2 += w0 * h0.x + w1 * h1.x + w2 * h2.x + w3 * h3.x;
            a3 += w0 * h0.y + w1 * h1.y + w2 * h2.y + w3 * h3.y;
        }
        for (; j < nn; j++) {
            int   s = __shfl_sync(0xffffffffu, idx, j);
            float ww = __shfl_sync(0xffffffffu, w, j);
            uint2 v = fb[(size_t)s * 32 + lane];
            float2 lo = __half22float2(*(__half2*)&v.x), hi = __half22float2(*(__half2*)&v.y);
            a0 += ww * lo.x; a1 += ww * lo.y; a2 += ww * hi.x; a3 += ww * hi.y;
        }
    }

    float dv = g_dinv[node], dv2 = dv * dv;
    uint2 sv = fb[(size_t)node * 32 + lane];
    float2 sl = __half22float2(*(__half2*)&sv.x), sh = __half22float2(*(__half2*)&sv.y);
    a0 = dv * a0 + dv2 * sl.x;
    a1 = dv * a1 + dv2 * sl.y;
    a2 = dv * a2 + dv2 * sh.x;
    a3 = dv * a3 + dv2 * sh.y;
    uint2 o;
    *(__half2*)&o.x = __floats2half2_rn(a0, a1);
    *(__half2*)&o.y = __floats2half2_rn(a2, a3);
    ((uint2*)A)[(size_t)node * 32 + lane] = o;
}

// layer 2: F=256 -> each lane owns 16B (uint4 = 4 half2)
__global__ void __launch_bounds__(256)
agg2_kernel(const __half* __restrict__ feat, __half* __restrict__ A) {
    cudaGridDependencySynchronize();
    int node = blockIdx.x * 8 + (threadIdx.x >> 5);
    if (node >= N_NODES) return;
    int lane = threadIdx.x & 31;
    int deg = g_deg[node];
    const int* cbase = g_col + (size_t)node * CSTRIDE;

    const uint4* fb = (const uint4*)feat;   // 32 uint4 per row
    float ac[8];
#pragma unroll
    for (int t = 0; t < 8; t++) ac[t] = 0.f;

    for (int cs = 0; cs < deg; cs += 32) {
        int nn = deg - cs; if (nn > 32) nn = 32;
        int idx = 0; float w = 0.f;
        if (lane < nn) { idx = cbase[cs + lane]; w = g_dinv[idx]; }
        int j = 0;
        for (; j + 4 <= nn; j += 4) {
            int   s0 = __shfl_sync(0xffffffffu, idx, j);
            int   s1 = __shfl_sync(0xffffffffu, idx, j + 1);
            int   s2 = __shfl_sync(0xffffffffu, idx, j + 2);
            int   s3 = __shfl_sync(0xffffffffu, idx, j + 3);
            float w0 = __shfl_sync(0xffffffffu, w, j);
            float w1 = __shfl_sync(0xffffffffu, w, j + 1);
            float w2 = __shfl_sync(0xffffffffu, w, j + 2);
            float w3 = __shfl_sync(0xffffffffu, w, j + 3);
            uint4 v0 = fb[(size_t)s0 * 32 + lane];
            uint4 v1 = fb[(size_t)s1 * 32 + lane];
            uint4 v2 = fb[(size_t)s2 * 32 + lane];
            uint4 v3 = fb[(size_t)s3 * 32 + lane];
            const unsigned* p0 = &v0.x; const unsigned* p1 = &v1.x;
            const unsigned* p2 = &v2.x; const unsigned* p3 = &v3.x;
#pragma unroll
            for (int t = 0; t < 4; t++) {
                float2 f0 = __half22float2(*(__half2*)&p0[t]);
                float2 f1 = __half22float2(*(__half2*)&p1[t]);
                float2 f2 = __half22float2(*(__half2*)&p2[t]);
                float2 f3 = __half22float2(*(__half2*)&p3[t]);
                ac[2 * t]     += w0 * f0.x + w1 * f1.x + w2 * f2.x + w3 * f3.x;
                ac[2 * t + 1] += w0 * f0.y + w1 * f1.y + w2 * f2.y + w3 * f3.y;
            }
        }
        for (; j < nn; j++) {
            int   s = __shfl_sync(0xffffffffu, idx, j);
            float ww = __shfl_sync(0xffffffffu, w, j);
            uint4 v = fb[(size_t)s * 32 + lane];
            const unsigned* p = &v.x;
#pragma unroll
            for (int t = 0; t < 4; t++) {
                float2 f = __half22float2(*(__half2*)&p[t]);
                ac[2 * t]     += ww * f.x;
                ac[2 * t + 1] += ww * f.y;
            }
        }
    }

    float dv = g_dinv[node], dv2 = dv * dv;
    uint4 sv = fb[(size_t)node * 32 + lane];
    const unsigned* sp = &sv.x;
    uint4 o;
    unsigned* op = &o.x;
#pragma unroll
    for (int t = 0; t < 4; t++) {
        float2 f = __half22float2(*(__half2*)&sp[t]);
        float vx = dv * ac[2 * t]     + dv2 * f.x;
        float vy = dv * ac[2 * t + 1] + dv2 * f.y;
        *(__half2*)&op[t] = __floats2half2_rn(vx, vy);
    }
    ((uint4*)A)[(size_t)node * 32 + lane] = o;
}

// ---------------- pipelined mma.sync fp16 GEMM (128x128, 256 thr, occ 2) ----------------
// C[M,256] = A[M,KE] @ B^T[256,KE] (+bias, relu)
#define ROWP 40
#define STAGE_ELEMS (128 * ROWP)

template <int KE>
__device__ __forceinline__ void gemm_issue(const __half* __restrict__ A,
                                           const __half* __restrict__ B,
                                           __half* sA, __half* sB,
                                           int row0, int col0, int kt, int tid) {
    int buf = kt % 3;
#pragma unroll
    for (int j = 0; j < 2; j++) {
        int i = tid + 256 * j;
        int r = i >> 2, q = i & 3;
        const __half* src = A + (size_t)(row0 + r) * KE + kt * 32 + q * 8;
        uint32_t dst = smem_to_u32(sA + buf * STAGE_ELEMS + r * ROWP + q * 8);
        CP_ASYNC16(dst, src);
    }
#pragma unroll
    for (int j = 0; j < 2; j++) {
        int i = tid + 256 * j;
        int r = i >> 2, q = i & 3;
        const __half* src = B + (size_t)(col0 + r) * KE + kt * 32 + q * 8;
        uint32_t dst = smem_to_u32(sB + buf * STAGE_ELEMS + r * ROWP + q * 8);
        CP_ASYNC16(dst, src);
    }
}

template <int KE, bool HALF_OUT>
__global__ void __launch_bounds__(256, 2)
mma_gemm_kernel(const __half* __restrict__ A, const __half* __restrict__ B,
                const float* __restrict__ bias, float* __restrict__ Cf,
                __half* __restrict__ Ch, int Mstore, int doRelu) {
    extern __shared__ __half sm[];
    __half* sA = sm;                      // [3][128][ROWP]
    __half* sB = sm + 3 * STAGE_ELEMS;    // [3][128][ROWP]

    cudaGridDependencySynchronize();

    int tid  = threadIdx.x;
    int lane = tid & 31;
    int warp = tid >> 5;
    int wm = warp >> 1, wn = warp & 1;
    int g = lane >> 2, c = lane & 3;

    int row0 = blockIdx.y * 128;
    int col0 = blockIdx.x * 128;

    float acc[2][8][4];
#pragma unroll
    for (int i = 0; i < 2; i++)
#pragma unroll
        for (int j = 0; j < 8; j++)
#pragma unroll
            for (int t = 0; t < 4; t++) acc[i][j][t] = 0.f;

    const int NK = KE / 32;

    gemm_issue<KE>(A, B, sA, sB, row0, col0, 0, tid);
    CP_COMMIT();
    gemm_issue<KE>(A, B, sA, sB, row0, col0, 1, tid);
    CP_COMMIT();

    for (int kt = 0; kt < NK; kt++) {
        int buf = kt % 3;
        CP_WAIT1();
        __syncthreads();

        const __half* bufA = sA + buf * STAGE_ELEMS;
        const __half* bufB = sB + buf * STAGE_ELEMS;
#pragma unroll
        for (int ks = 0; ks < 2; ks++) {
            int kb = ks * 16 + c * 2;
            unsigned af[2][4];
#pragma unroll
            for (int i = 0; i < 2; i++) {
                const __half* pa = bufA + (wm * 32 + i * 16 + g) * ROWP + kb;
                af[i][0] = *(const unsigned*)pa;
                af[i][1] = *(const unsigned*)(pa + 8 * ROWP);
                af[i][2] = *(const unsigned*)(pa + 8);
                af[i][3] = *(const unsigned*)(pa + 8 * ROWP + 8);
            }
#pragma unroll
            for (int j = 0; j < 8; j++) {
                const __half* pb = bufB + (wn * 64 + j * 8 + g) * ROWP + kb;
                unsigned bfr[2];
                bfr[0] = *(const unsigned*)pb;
                bfr[1] = *(const unsigned*)(pb + 8);
                MMA_F16(acc[0][j], af[0], bfr);
                MMA_F16(acc[1][j], af[1], bfr);
            }
        }

        if (kt + 2 < NK)
            gemm_issue<KE>(A, B, sA, sB, row0, col0, kt + 2, tid);
        CP_COMMIT();   // empty commits at tail keep group numbering aligned
    }

    // epilogue
#pragma unroll
    for (int i = 0; i < 2; i++) {
        int r0 = row0 + wm * 32 + i * 16 + g;
        int r1 = r0 + 8;
#pragma unroll
        for (int j = 0; j < 8; j++) {
            int col = col0 + wn * 64 + j * 8 + c * 2;
            float bx = bias[col], by = bias[col + 1];
            float2 v0 = make_float2(acc[i][j][0] + bx, acc[i][j][1] + by);
            float2 v1 = make_float2(acc[i][j][2] + bx, acc[i][j][3] + by);
            if (doRelu) {
                v0.x = fmaxf(v0.x, 0.f); v0.y = fmaxf(v0.y, 0.f);
                v1.x = fmaxf(v1.x, 0.f); v1.y = fmaxf(v1.y, 0.f);
            }
            if (HALF_OUT) {
                if (r0 < Mstore) *(__half2*)&Ch[(size_t)r0 * 256 + col] = __floats2half2_rn(v0.x, v0.y);
                if (r1 < Mstore) *(__half2*)&Ch[(size_t)r1 * 256 + col] = __floats2half2_rn(v1.x, v1.y);
            } else {
                if (r0 < Mstore) *(float2*)&Cf[(size_t)r0 * 256 + col] = v0;
                if (r1 < Mstore) *(float2*)&Cf[(size_t)r1 * 256 + col] = v1;
            }
        }
    }
}

#define SMEM_GEMM (6 * STAGE_ELEMS * (int)sizeof(__half))   // 61440

// ---------------- launch ----------------
extern "C" void kernel_launch(void* const* d_in, const int* in_sizes, int n_in,
                              void* d_out, int out_size) {
    const float* x   = (const float*)d_in[0];
    const void*  ei  = d_in[1];
    const float* W1  = (const float*)d_in[2];
    const float* b1  = (const float*)d_in[3];
    const float* W2  = (const float*)d_in[4];
    const float* b2  = (const float*)d_in[5];
    float*       out = (float*)d_out;

    __half *x16, *a1, *a2, *w1t, *w2t, *h;
    cudaGetSymbolAddress((void**)&x16, g_x16);
    cudaGetSymbolAddress((void**)&a1,  g_a1);
    cudaGetSymbolAddress((void**)&a2,  g_a2);
    cudaGetSymbolAddress((void**)&h,   g_h);
    cudaGetSymbolAddress((void**)&w1t, g_w1t);
    cudaGetSymbolAddress((void**)&w2t, g_w2t);

    cudaFuncSetAttribute(mma_gemm_kernel<IN_CH, true>,
                         cudaFuncAttributeMaxDynamicSharedMemorySize, SMEM_GEMM);
    cudaFuncSetAttribute(mma_gemm_kernel<HID, false>,
                         cudaFuncAttributeMaxDynamicSharedMemorySize, SMEM_GEMM);

    // one-time stream/event creation (host-side resources; per-call work unchanged)
    static cudaStream_t s_prep = nullptr;
    static cudaEvent_t  s_evF = nullptr, s_evJ = nullptr;
    if (!s_prep) {
        cudaStreamCreateWithFlags(&s_prep, cudaStreamNonBlocking);
        cudaEventCreateWithFlags(&s_evF, cudaEventDisableTiming);
        cudaEventCreateWithFlags(&s_evJ, cudaEventDisableTiming);
    }

    // fork: operand prep runs concurrent with graph build
    cudaEventRecord(s_evF, 0);
    cudaStreamWaitEvent(s_prep, s_evF, 0);
    x2h_kernel<<<(N_NODES * IN_CH / 4 + 255) / 256, 256, 0, s_prep>>>(x, x16);
    roundW_kernel<<<(IN_CH * 256 + 255) / 256, 256, 0, s_prep>>>(W1, IN_CH, w1t);
    roundW_kernel<<<(HID * 256 + 255) / 256, 256, 0, s_prep>>>(W2, HID, w2t);
    cudaEventRecord(s_evJ, s_prep);

    // PDL launch attribute (secondary may pre-launch; kernel syncs before dependent reads)
    cudaLaunchAttribute pdlAttr[1];
    pdlAttr[0].id = cudaLaunchAttributeProgrammaticStreamSerialization;
    pdlAttr[0].val.programmaticStreamSerializationAllowed = 1;

    // main stream: graph build (2 kernels; cnt==0 invariant maintained by dinv)
    histfill_kernel<<<(N_EDGES + 256 * EILP - 1) / (256 * EILP), 256>>>((const int*)ei);
    {
        cudaLaunchConfig_t cfg = {};
        cfg.gridDim = dim3((N_NODES + 255) / 256);
        cfg.blockDim = dim3(256);
        cfg.stream = 0;
        cfg.attrs = pdlAttr; cfg.numAttrs = 1;
        cudaLaunchKernelEx(&cfg, dinv_kernel);
    }

    // join
    cudaStreamWaitEvent(0, s_evJ, 0);

    // layer 1: a1 = A_norm @ x16 ; h = relu(a1 @ W1 + b1) -> fp16
    {
        cudaLaunchConfig_t cfg = {};
        cfg.gridDim = dim3((N_NODES + 7) / 8);
        cfg.blockDim = dim3(256);
        cfg.stream = 0;
        cfg.attrs = pdlAttr; cfg.numAttrs = 1;
        cudaLaunchKernelEx(&cfg, agg1_kernel, (const __half*)x16, a1);
    }
    {
        cudaLaunchConfig_t cfg = {};
        cfg.gridDim = dim3(2, MPAD / 128);
        cfg.blockDim = dim3(256);
        cfg.dynamicSmemBytes = SMEM_GEMM;
        cfg.stream = 0;
        cfg.attrs = pdlAttr; cfg.numAttrs = 1;
        cudaLaunchKernelEx(&cfg, mma_gemm_kernel<IN_CH, true>,
                           (const __half*)a1, (const __half*)w1t, b1,
                           (float*)nullptr, h, (int)MPAD, 1);
    }

    // layer 2: a2 = A_norm @ h ; out = a2 @ W2 + b2 -> fp32
    {
        cudaLaunchConfig_t cfg = {};
        cfg.gridDim = dim3((N_NODES + 7) / 8);
        cfg.blockDim = dim3(256);
        cfg.stream = 0;
        cfg.attrs = pdlAttr; cfg.numAttrs = 1;
        cudaLaunchKernelEx(&cfg, agg2_kernel, (const __half*)h, a2);
    }
    {
        cudaLaunchConfig_t cfg = {};
        cfg.gridDim = dim3(2, MPAD / 128);
        cfg.blockDim = dim3(256);
        cfg.dynamicSmemBytes = SMEM_GEMM;
        cfg.stream = 0;
        cfg.attrs = pdlAttr; cfg.numAttrs = 1;
        cudaLaunchKernelEx(&cfg, mma_gemm_kernel<HID, false>,
                           (const __half*)a2, (const __half*)w2t, b2,
                           out, (__half*)nullptr, (int)N_NODES, 0);
    }
}

// round 16
// speedup vs baseline: 1.0053x; 1.0053x over previous
#include <cuda_runtime.h>
#include <cuda_fp16.h>
#include <math.h>
#include <stdint.h>

#define N_NODES 50000
#define N_EDGES 800000
#define IN_CH   128
#define HID     256
#define MPAD    50048   // 391 * 128
#define CSTRIDE 128     // padded-CSR slots per node (P(deg>=128) ~ 0)

// ---------------- scratch (device globals; zero-initialized bss) ----------------
__device__ int   g_cnt[N_NODES];     // invariant: all-zero at kernel_launch entry
__device__ int   g_deg[N_NODES];
__device__ int   g_col[(size_t)N_NODES * CSTRIDE];
__device__ float g_dinv[N_NODES];

__device__ __half g_x16[(size_t)N_NODES * IN_CH];   // x rounded to fp16
__device__ __half g_a1[(size_t)MPAD * IN_CH];       // agg1 out (pad rows stay 0)
__device__ __half g_h[(size_t)MPAD * HID];          // relu(a1@W1+b1), fp16
__device__ __half g_a2[(size_t)MPAD * HID];         // agg2 out (pad rows stay 0)
__device__ __half g_w1t[HID * IN_CH];               // W1^T fp16 [256][128]
__device__ __half g_w2t[HID * HID];                 // W2^T fp16 [256][256]

// ---------------- helpers ----------------
__device__ __forceinline__ uint32_t smem_to_u32(const void* p) {
    uint32_t a;
    asm("{ .reg .u64 t; cvta.to.shared.u64 t, %1; cvt.u32.u64 %0, t; }" : "=r"(a) : "l"(p));
    return a;
}
#define CP_ASYNC16(dst, src) \
    asm volatile("cp.async.cg.shared.global [%0], [%1], 16;" :: "r"(dst), "l"(src))
#define CP_COMMIT() asm volatile("cp.async.commit_group;" ::: "memory")
#define CP_WAIT1()  asm volatile("cp.async.wait_group 1;" ::: "memory")

#define MMA_F16(acc, a, b) \
    asm volatile("mma.sync.aligned.m16n8k16.row.col.f32.f16.f16.f32 " \
                 "{%0,%1,%2,%3},{%4,%5,%6,%7},{%8,%9},{%0,%1,%2,%3};" \
                 : "+f"(acc[0]), "+f"(acc[1]), "+f"(acc[2]), "+f"(acc[3]) \
                 : "r"(a[0]), "r"(a[1]), "r"(a[2]), "r"(a[3]), "r"(b[0]), "r"(b[1]))

// ---------------- graph build: edge-parallel, 2 edges/thread vectorized -----------
// int64 little-endian with values < 50000 => first 128 odd int32 words all zero.
__global__ void __launch_bounds__(256)
histfill_kernel(const int* __restrict__ ei_raw) {
    __shared__ int s_bad;
    if (threadIdx.x == 0) s_bad = 0;
    __syncthreads();
    if (threadIdx.x < 128 && ei_raw[2 * threadIdx.x + 1] != 0) s_bad = 1;
    __syncthreads();
    bool is64 = (s_bad == 0);

    int i = blockIdx.x * 256 + threadIdx.x;     // pair index: edges 2i, 2i+1
    if (2 * i >= N_EDGES) return;
    int s0, s1, d0, d1;
    if (is64) {
        longlong2 sp = ((const longlong2*)ei_raw)[i];
        longlong2 dp = ((const longlong2*)ei_raw)[N_EDGES / 2 + i];
        s0 = (int)sp.x; s1 = (int)sp.y;
        d0 = (int)dp.x; d1 = (int)dp.y;
    } else {
        int2 sp = ((const int2*)ei_raw)[i];
        int2 dp = ((const int2*)ei_raw)[N_EDGES / 2 + i];
        s0 = sp.x; s1 = sp.y;
        d0 = dp.x; d1 = dp.y;
    }
    int p0 = atomicAdd(&g_cnt[d0], 1);
    int p1 = atomicAdd(&g_cnt[d1], 1);
    if (p0 < CSTRIDE) g_col[(size_t)d0 * CSTRIDE + p0] = s0;
    if (p1 < CSTRIDE) g_col[(size_t)d1 * CSTRIDE + p1] = s1;
}
// deg/dinv + reset cnt for next graph replay
__global__ void dinv_kernel() {
    cudaGridDependencySynchronize();
    int i = blockIdx.x * blockDim.x + threadIdx.x;
    if (i < N_NODES) {
        int c = g_cnt[i];
        g_deg[i]  = (c < CSTRIDE) ? c : CSTRIDE;
        g_dinv[i] = rsqrtf((float)(c + 1));
        g_cnt[i]  = 0;
    }
}

// ---------------- x -> fp16 ----------------
__global__ void x2h_kernel(const float* __restrict__ x, __half* __restrict__ xh) {
    int i = blockIdx.x * blockDim.x + threadIdx.x;   // one float4 per thread
    if (i < N_NODES * IN_CH / 4) {
        float4 v = ((const float4*)x)[i];
        ((__half2*)xh)[2 * i]     = __floats2half2_rn(v.x, v.y);
        ((__half2*)xh)[2 * i + 1] = __floats2half2_rn(v.z, v.w);
    }
}

// ---------------- W round+transpose: W [K][256] fp32 -> WT [256][K] fp16 ----------------
__global__ void roundW_kernel(const float* __restrict__ W, int K, __half* __restrict__ WT) {
    int idx = blockIdx.x * 256 + threadIdx.x;
    if (idx < K * 256) {
        int k = idx >> 8, n = idx & 255;
        WT[(size_t)n * K + k] = __float2half_rn(W[idx]);
    }
}

// ---------------- warp-per-node aggregation (padded CSR) ----------------
// out[v] = dinv[v]*sum dinv[s]*feat[s] + dinv[v]^2*feat[v]; 8 nodes per 256-thr block.

// layer 1: F=128 -> each lane owns 8B (uint2 = 2 half2)
__global__ void __launch_bounds__(256)
agg1_kernel(const __half* __restrict__ feat, __half* __restrict__ A) {
    cudaGridDependencySynchronize();
    int node = blockIdx.x * 8 + (threadIdx.x >> 5);
    if (node >= N_NODES) return;
    int lane = threadIdx.x & 31;
    int deg = g_deg[node];
    const int* cbase = g_col + (size_t)node * CSTRIDE;

    const uint2* fb = (const uint2*)feat;   // 32 uint2 per row
    float a0 = 0.f, a1 = 0.f, a2 = 0.f, a3 = 0.f;

    for (int cs = 0; cs < deg; cs += 32) {
        int nn = deg - cs; if (nn > 32) nn = 32;
        int idx = 0; float w = 0.f;
        if (lane < nn) { idx = cbase[cs + lane]; w = g_dinv[idx]; }
        int j = 0;
        for (; j + 4 <= nn; j += 4) {
            int   s0 = __shfl_sync(0xffffffffu, idx, j);
            int   s1 = __shfl_sync(0xffffffffu, idx, j + 1);
            int   s2 = __shfl_sync(0xffffffffu, idx, j + 2);
            int   s3 = __shfl_sync(0xffffffffu, idx, j + 3);
            float w0 = __shfl_sync(0xffffffffu, w, j);
            float w1 = __shfl_sync(0xffffffffu, w, j + 1);
            float w2 = __shfl_sync(0xffffffffu, w, j + 2);
            float w3 = __shfl_sync(0xffffffffu, w, j + 3);
            uint2 v0 = fb[(size_t)s0 * 32 + lane];
            uint2 v1 = fb[(size_t)s1 * 32 + lane];
            uint2 v2 = fb[(size_t)s2 * 32 + lane];
            uint2 v3 = fb[(size_t)s3 * 32 + lane];
            float2 l0 = __half22float2(*(__half2*)&v0.x), h0 = __half22float2(*(__half2*)&v0.y);
            float2 l1 = __half22float2(*(__half2*)&v1.x), h1 = __half22float2(*(__half2*)&v1.y);
            float2 l2 = __half22float2(*(__half2*)&v2.x), h2 = __half22float2(*(__half2*)&v2.y);
            float2 l3 = __half22float2(*(__half2*)&v3.x), h3 = __half22float2(*(__half2*)&v3.y);
            a0 += w0 * l0.x + w1 * l1.x + w2 * l2.x + w3 * l3.x;
            a1 += w0 * l0.y + w1 * l1.y + w2 * l2.y + w3 * l3.y;
            a2 += w0 * h0.x + w1 * h1.x + w2 * h2.x + w3 * h3.x;
            a3 += w0 * h0.y + w1 * h1.y + w2 * h2.y + w3 * h3.y;
        }
        for (; j < nn; j++) {
            int   s = __shfl_sync(0xffffffffu, idx, j);
            float ww = __shfl_sync(0xffffffffu, w, j);
            uint2 v = fb[(size_t)s * 32 + lane];
            float2 lo = __half22float2(*(__half2*)&v.x), hi = __half22float2(*(__half2*)&v.y);
            a0 += ww * lo.x; a1 += ww * lo.y; a2 += ww * hi.x; a3 += ww * hi.y;
        }
    }

    float dv = g_dinv[node], dv2 = dv * dv;
    uint2 sv = fb[(size_t)node * 32 + lane];
    float2 sl = __half22float2(*(__half2*)&sv.x), sh = __half22float2(*(__half2*)&sv.y);
    a0 = dv * a0 + dv2 * sl.x;
    a1 = dv * a1 + dv2 * sl.y;
    a2 = dv * a2 + dv2 * sh.x;
    a3 = dv * a3 + dv2 * sh.y;
    uint2 o;
    *(__half2*)&o.x = __floats2half2_rn(a0, a1);
    *(__half2*)&o.y = __floats2half2_rn(a2, a3);
    ((uint2*)A)[(size_t)node * 32 + lane] = o;
}

// layer 2: F=256 -> each lane owns 16B (uint4 = 4 half2)
__global__ void __launch_bounds__(256)
agg2_kernel(const __half* __restrict__ feat, __half* __restrict__ A) {
    cudaGridDependencySynchronize();
    int node = blockIdx.x * 8 + (threadIdx.x >> 5);
    if (node >= N_NODES) return;
    int lane = threadIdx.x & 31;
    int deg = g_deg[node];
    const int* cbase = g_col + (size_t)node * CSTRIDE;

    const uint4* fb = (const uint4*)feat;   // 32 uint4 per row
    float ac[8];
#pragma unroll
    for (int t = 0; t < 8; t++) ac[t] = 0.f;

    for (int cs = 0; cs < deg; cs += 32) {
        int nn = deg - cs; if (nn > 32) nn = 32;
        int idx = 0; float w = 0.f;
        if (lane < nn) { idx = cbase[cs + lane]; w = g_dinv[idx]; }
        int j = 0;
        for (; j + 4 <= nn; j += 4) {
            int   s0 = __shfl_sync(0xffffffffu, idx, j);
            int   s1 = __shfl_sync(0xffffffffu, idx, j + 1);
            int   s2 = __shfl_sync(0xffffffffu, idx, j + 2);
            int   s3 = __shfl_sync(0xffffffffu, idx, j + 3);
            float w0 = __shfl_sync(0xffffffffu, w, j);
            float w1 = __shfl_sync(0xffffffffu, w, j + 1);
            float w2 = __shfl_sync(0xffffffffu, w, j + 2);
            float w3 = __shfl_sync(0xffffffffu, w, j + 3);
            uint4 v0 = fb[(size_t)s0 * 32 + lane];
            uint4 v1 = fb[(size_t)s1 * 32 + lane];
            uint4 v2 = fb[(size_t)s2 * 32 + lane];
            uint4 v3 = fb[(size_t)s3 * 32 + lane];
            const unsigned* p0 = &v0.x; const unsigned* p1 = &v1.x;
            const unsigned* p2 = &v2.x; const unsigned* p3 = &v3.x;
#pragma unroll
            for (int t = 0; t < 4; t++) {
                float2 f0 = __half22float2(*(__half2*)&p0[t]);
                float2 f1 = __half22float2(*(__half2*)&p1[t]);
                float2 f2 = __half22float2(*(__half2*)&p2[t]);
                float2 f3 = __half22float2(*(__half2*)&p3[t]);
                ac[2 * t]     += w0 * f0.x + w1 * f1.x + w2 * f2.x + w3 * f3.x;
                ac[2 * t + 1] += w0 * f0.y + w1 * f1.y + w2 * f2.y + w3 * f3.y;
            }
        }
        for (; j < nn; j++) {
            int   s = __shfl_sync(0xffffffffu, idx, j);
            float ww = __shfl_sync(0xffffffffu, w, j);
            uint4 v = fb[(size_t)s * 32 + lane];
            const unsigned* p = &v.x;
#pragma unroll
            for (int t = 0; t < 4; t++) {
                float2 f = __half22float2(*(__half2*)&p[t]);
                ac[2 * t]     += ww * f.x;
                ac[2 * t + 1] += ww * f.y;
            }
        }
    }

    float dv = g_dinv[node], dv2 = dv * dv;
    uint4 sv = fb[(size_t)node * 32 + lane];
    const unsigned* sp = &sv.x;
    uint4 o;
    unsigned* op = &o.x;
#pragma unroll
    for (int t = 0; t < 4; t++) {
        float2 f = __half22float2(*(__half2*)&sp[t]);
        float vx = dv * ac[2 * t]     + dv2 * f.x;
        float vy = dv * ac[2 * t + 1] + dv2 * f.y;
        *(__half2*)&op[t] = __floats2half2_rn(vx, vy);
    }
    ((uint4*)A)[(size_t)node * 32 + lane] = o;
}

// ---------------- pipelined mma.sync fp16 GEMM (128x128, 256 thr, occ 2) ----------------
// C[M,256] = A[M,KE] @ B^T[256,KE] (+bias, relu)
#define ROWP 40
#define STAGE_ELEMS (128 * ROWP)

template <int KE>
__device__ __forceinline__ void gemm_issue(const __half* __restrict__ A,
                                           const __half* __restrict__ B,
                                           __half* sA, __half* sB,
                                           int row0, int col0, int kt, int tid) {
    int buf = kt % 3;
#pragma unroll
    for (int j = 0; j < 2; j++) {
        int i = tid + 256 * j;
        int r = i >> 2, q = i & 3;
        const __half* src = A + (size_t)(row0 + r) * KE + kt * 32 + q * 8;
        uint32_t dst = smem_to_u32(sA + buf * STAGE_ELEMS + r * ROWP + q * 8);
        CP_ASYNC16(dst, src);
    }
#pragma unroll
    for (int j = 0; j < 2; j++) {
        int i = tid + 256 * j;
        int r = i >> 2, q = i & 3;
        const __half* src = B + (size_t)(col0 + r) * KE + kt * 32 + q * 8;
        uint32_t dst = smem_to_u32(sB + buf * STAGE_ELEMS + r * ROWP + q * 8);
        CP_ASYNC16(dst, src);
    }
}

template <int KE, bool HALF_OUT>
__global__ void __launch_bounds__(256, 2)
mma_gemm_kernel(const __half* __restrict__ A, const __half* __restrict__ B,
                const float* __restrict__ bias, float* __restrict__ Cf,
                __half* __restrict__ Ch, int Mstore, int doRelu) {
    extern __shared__ __half sm[];
    __half* sA = sm;                      // [3][128][ROWP]
    __half* sB = sm + 3 * STAGE_ELEMS;    // [3][128][ROWP]

    cudaGridDependencySynchronize();

    int tid  = threadIdx.x;
    int lane = tid & 31;
    int warp = tid >> 5;
    int wm = warp >> 1, wn = warp & 1;
    int g = lane >> 2, c = lane & 3;

    int row0 = blockIdx.y * 128;
    int col0 = blockIdx.x * 128;

    float acc[2][8][4];
#pragma unroll
    for (int i = 0; i < 2; i++)
#pragma unroll
        for (int j = 0; j < 8; j++)
#pragma unroll
            for (int t = 0; t < 4; t++) acc[i][j][t] = 0.f;

    const int NK = KE / 32;

    gemm_issue<KE>(A, B, sA, sB, row0, col0, 0, tid);
    CP_COMMIT();
    gemm_issue<KE>(A, B, sA, sB, row0, col0, 1, tid);
    CP_COMMIT();

    for (int kt = 0; kt < NK; kt++) {
        int buf = kt % 3;
        CP_WAIT1();
        __syncthreads();

        const __half* bufA = sA + buf * STAGE_ELEMS;
        const __half* bufB = sB + buf * STAGE_ELEMS;
#pragma unroll
        for (int ks = 0; ks < 2; ks++) {
            int kb = ks * 16 + c * 2;
            unsigned af[2][4];
#pragma unroll
            for (int i = 0; i < 2; i++) {
                const __half* pa = bufA + (wm * 32 + i * 16 + g) * ROWP + kb;
                af[i][0] = *(const unsigned*)pa;
                af[i][1] = *(const unsigned*)(pa + 8 * ROWP);
                af[i][2] = *(const unsigned*)(pa + 8);
                af[i][3] = *(const unsigned*)(pa + 8 * ROWP + 8);
            }
#pragma unroll
            for (int j = 0; j < 8; j++) {
                const __half* pb = bufB + (wn * 64 + j * 8 + g) * ROWP + kb;
                unsigned bfr[2];
                bfr[0] = *(const unsigned*)pb;
                bfr[1] = *(const unsigned*)(pb + 8);
                MMA_F16(acc[0][j], af[0], bfr);
                MMA_F16(acc[1][j], af[1], bfr);
            }
        }

        if (kt + 2 < NK)
            gemm_issue<KE>(A, B, sA, sB, row0, col0, kt + 2, tid);
        CP_COMMIT();   // empty commits at tail keep group numbering aligned
    }

    // epilogue
#pragma unroll
    for (int i = 0; i < 2; i++) {
        int r0 = row0 + wm * 32 + i * 16 + g;
        int r1 = r0 + 8;
#pragma unroll
        for (int j = 0; j < 8; j++) {
            int col = col0 + wn * 64 + j * 8 + c * 2;
            float bx = bias[col], by = bias[col + 1];
            float2 v0 = make_float2(acc[i][j][0] + bx, acc[i][j][1] + by);
            float2 v1 = make_float2(acc[i][j][2] + bx, acc[i][j][3] + by);
            if (doRelu) {
                v0.x = fmaxf(v0.x, 0.f); v0.y = fmaxf(v0.y, 0.f);
                v1.x = fmaxf(v1.x, 0.f); v1.y = fmaxf(v1.y, 0.f);
            }
            if (HALF_OUT) {
                if (r0 < Mstore) *(__half2*)&Ch[(size_t)r0 * 256 + col] = __floats2half2_rn(v0.x, v0.y);
                if (r1 < Mstore) *(__half2*)&Ch[(size_t)r1 * 256 + col] = __floats2half2_rn(v1.x, v1.y);
            } else {
                if (r0 < Mstore) *(float2*)&Cf[(size_t)r0 * 256 + col] = v0;
                if (r1 < Mstore) *(float2*)&Cf[(size_t)r1 * 256 + col] = v1;
            }
        }
    }
}

#define SMEM_GEMM (6 * STAGE_ELEMS * (int)sizeof(__half))   // 61440

// ---------------- launch ----------------
extern "C" void kernel_launch(void* const* d_in, const int* in_sizes, int n_in,
                              void* d_out, int out_size) {
    const float* x   = (const float*)d_in[0];
    const void*  ei  = d_in[1];
    const float* W1  = (const float*)d_in[2];
    const float* b1  = (const float*)d_in[3];
    const float* W2  = (const float*)d_in[4];
    const float* b2  = (const float*)d_in[5];
    float*       out = (float*)d_out;

    __half *x16, *a1, *a2, *w1t, *w2t, *h;
    cudaGetSymbolAddress((void**)&x16, g_x16);
    cudaGetSymbolAddress((void**)&a1,  g_a1);
    cudaGetSymbolAddress((void**)&a2,  g_a2);
    cudaGetSymbolAddress((void**)&h,   g_h);
    cudaGetSymbolAddress((void**)&w1t, g_w1t);
    cudaGetSymbolAddress((void**)&w2t, g_w2t);

    cudaFuncSetAttribute(mma_gemm_kernel<IN_CH, true>,
                         cudaFuncAttributeMaxDynamicSharedMemorySize, SMEM_GEMM);
    cudaFuncSetAttribute(mma_gemm_kernel<HID, false>,
                         cudaFuncAttributeMaxDynamicSharedMemorySize, SMEM_GEMM);

    // one-time stream/event creation (host-side resources; per-call work unchanged)
    static cudaStream_t s_prep = nullptr;
    static cudaEvent_t  s_evF = nullptr, s_evJ = nullptr;
    if (!s_prep) {
        cudaStreamCreateWithFlags(&s_prep, cudaStreamNonBlocking);
        cudaEventCreateWithFlags(&s_evF, cudaEventDisableTiming);
        cudaEventCreateWithFlags(&s_evJ, cudaEventDisableTiming);
    }

    // fork: operand prep runs concurrent with graph build
    cudaEventRecord(s_evF, 0);
    cudaStreamWaitEvent(s_prep, s_evF, 0);
    x2h_kernel<<<(N_NODES * IN_CH / 4 + 255) / 256, 256, 0, s_prep>>>(x, x16);
    roundW_kernel<<<(IN_CH * 256 + 255) / 256, 256, 0, s_prep>>>(W1, IN_CH, w1t);
    roundW_kernel<<<(HID * 256 + 255) / 256, 256, 0, s_prep>>>(W2, HID, w2t);
    cudaEventRecord(s_evJ, s_prep);

    // PDL launch attribute (secondary may pre-launch; kernel syncs before dependent reads)
    cudaLaunchAttribute pdlAttr[1];
    pdlAttr[0].id = cudaLaunchAttributeProgrammaticStreamSerialization;
    pdlAttr[0].val.programmaticStreamSerializationAllowed = 1;

    // main stream: graph build (2 kernels; cnt==0 invariant maintained by dinv)
    histfill_kernel<<<(N_EDGES / 2 + 255) / 256, 256>>>((const int*)ei);
    {
        cudaLaunchConfig_t cfg = {};
        cfg.gridDim = dim3((N_NODES + 255) / 256);
        cfg.blockDim = dim3(256);
        cfg.stream = 0;
        cfg.attrs = pdlAttr; cfg.numAttrs = 1;
        cudaLaunchKernelEx(&cfg, dinv_kernel);
    }

    // join
    cudaStreamWaitEvent(0, s_evJ, 0);

    // layer 1: a1 = A_norm @ x16 ; h = relu(a1 @ W1 + b1) -> fp16
    {
        cudaLaunchConfig_t cfg = {};
        cfg.gridDim = dim3((N_NODES + 7) / 8);
        cfg.blockDim = dim3(256);
        cfg.stream = 0;
        cfg.attrs = pdlAttr; cfg.numAttrs = 1;
        cudaLaunchKernelEx(&cfg, agg1_kernel, (const __half*)x16, a1);
    }
    {
        cudaLaunchConfig_t cfg = {};
        cfg.gridDim = dim3(2, MPAD / 128);
        cfg.blockDim = dim3(256);
        cfg.dynamicSmemBytes = SMEM_GEMM;
        cfg.stream = 0;
        cfg.attrs = pdlAttr; cfg.numAttrs = 1;
        cudaLaunchKernelEx(&cfg, mma_gemm_kernel<IN_CH, true>,
                           (const __half*)a1, (const __half*)w1t, b1,
                           (float*)nullptr, h, (int)MPAD, 1);
    }

    // layer 2: a2 = A_norm @ h ; out = a2 @ W2 + b2 -> fp32
    {
        cudaLaunchConfig_t cfg = {};
        cfg.gridDim = dim3((N_NODES + 7) / 8);
        cfg.blockDim = dim3(256);
        cfg.stream = 0;
        cfg.attrs = pdlAttr; cfg.numAttrs = 1;
        cudaLaunchKernelEx(&cfg, agg2_kernel, (const __half*)h, a2);
    }
    {
        cudaLaunchConfig_t cfg = {};
        cfg.gridDim = dim3(2, MPAD / 128);
        cfg.blockDim = dim3(256);
        cfg.dynamicSmemBytes = SMEM_GEMM;
        cfg.stream = 0;
        cfg.attrs = pdlAttr; cfg.numAttrs = 1;
        cudaLaunchKernelEx(&cfg, mma_gemm_kernel<HID, false>,
                           (const __half*)a2, (const __half*)w2t, b2,
                           out, (__half*)nullptr, (int)N_NODES, 0);
    }
}